// round 2
// baseline (speedup 1.0000x reference)
#include <cuda_runtime.h>

#define FDIM 64
#define WIN  16
#define BT   96
#define ROWS (BT + WIN - 1)   /* 111 */
#define NEG  0.2f

__global__ __launch_bounds__(256, 4)
void gat_kernel(const float* __restrict__ ori,
                const float* __restrict__ Wfc,
                const float* __restrict__ attn_l,
                const float* __restrict__ attn_r,
                const float* __restrict__ bias,
                float* __restrict__ out, int T)
{
    __shared__ __align__(16) float Wsh[FDIM][FDIM];   // [k][c]
    __shared__ __align__(16) float zsh[ROWS][FDIM];   // x tile, overwritten by z in place
    __shared__ __align__(16) float alsh[FDIM];
    __shared__ __align__(16) float arsh[FDIM];
    __shared__ __align__(16) float bsh[FDIM];
    __shared__ __align__(16) float elsh[ROWS];
    __shared__ __align__(16) float ersh[ROWS];

    const int tid = threadIdx.x;
    const int t0  = blockIdx.x * BT;

    // ---- stage W_fc (row-major [f][o]) ----
    for (int i = tid; i < FDIM * FDIM / 4; i += 256)
        ((float4*)Wsh)[i] = ((const float4*)Wfc)[i];
    if (tid < FDIM) {
        alsh[tid] = attn_l[tid];
        arsh[tid] = attn_r[tid];
        bsh[tid]  = bias[tid];
    }
    // ---- stage input rows [t0-15 .. t0+BT-1], clamped (left-pad semantics) ----
    for (int i = tid; i < ROWS * (FDIM / 4); i += 256) {
        int r  = i >> 4;          // row in tile
        int c4 = i & 15;          // float4 column
        int s  = t0 - (WIN - 1) + r;
        s = s < 0 ? 0 : (s > T - 1 ? T - 1 : s);
        ((float4*)zsh[r])[c4] =
            ((const float4*)(ori + (size_t)s * FDIM))[c4];
    }
    __syncthreads();

    // ---- GEMM: z[r][c] = sum_k x[r][k] * W[k][c]; 4 rows/warp-iter, 2 cols/lane ----
    const int warp = tid >> 5, lane = tid & 31;
    const float2 alv = *(const float2*)&alsh[2 * lane];
    const float2 arv = *(const float2*)&arsh[2 * lane];

    for (int base = warp * 4; base < ROWS; base += 32) {
        const float* rp[4];
        #pragma unroll
        for (int i = 0; i < 4; i++) {
            int rr = base + i;
            rp[i] = zsh[rr < ROWS ? rr : ROWS - 1];
        }
        float acc[4][2] = {{0.f,0.f},{0.f,0.f},{0.f,0.f},{0.f,0.f}};
        #pragma unroll 8
        for (int k = 0; k < FDIM; k++) {
            float2 wv = *(const float2*)&Wsh[k][2 * lane];
            #pragma unroll
            for (int i = 0; i < 4; i++) {
                float x = rp[i][k];
                acc[i][0] += x * wv.x;
                acc[i][1] += x * wv.y;
            }
        }
        // all reads of this warp's rows are done (in-order per warp) -> safe in-place write
        #pragma unroll
        for (int i = 0; i < 4; i++) {
            int rr = base + i;
            if (rr < ROWS)
                *(float2*)&zsh[rr][2 * lane] = make_float2(acc[i][0], acc[i][1]);
        }
        // el/er for these rows via butterfly reduction
        float el[4], er[4];
        #pragma unroll
        for (int i = 0; i < 4; i++) {
            el[i] = acc[i][0] * alv.x + acc[i][1] * alv.y;
            er[i] = acc[i][0] * arv.x + acc[i][1] * arv.y;
        }
        #pragma unroll
        for (int off = 16; off; off >>= 1) {
            #pragma unroll
            for (int i = 0; i < 4; i++) {
                el[i] += __shfl_xor_sync(0xffffffffu, el[i], off);
                er[i] += __shfl_xor_sync(0xffffffffu, er[i], off);
            }
        }
        if (lane == 0) {
            #pragma unroll
            for (int i = 0; i < 4; i++) {
                int rr = base + i;
                if (rr < ROWS) { elsh[rr] = el[i]; ersh[rr] = er[i]; }
            }
        }
    }
    __syncthreads();

    // ---- attention: dst node is the last window slot -> er of row (j+WIN-1) = er[t] ----
    const int g  = tid >> 4;   // 16 groups of 16 lanes
    const int gl = tid & 15;
    const float4 bv = *(const float4*)&bsh[4 * gl];

    for (int j = g; j < BT; j += 16) {
        int t = t0 + j;
        if (t >= T) break;
        float ert = ersh[j + WIN - 1];
        float ew[WIN];
        float m = -1e30f;
        #pragma unroll
        for (int u = 0; u < WIN; u++) {
            float e = elsh[j + u] + ert;
            e = (e > 0.f) ? e : NEG * e;
            ew[u] = e;
            m = fmaxf(m, e);
        }
        float ssum = 0.f;
        #pragma unroll
        for (int u = 0; u < WIN; u++) {
            float x = __expf(ew[u] - m);
            ew[u] = x;
            ssum += x;
        }
        float inv = 1.f / ssum;
        float4 acc = make_float4(0.f, 0.f, 0.f, 0.f);
        #pragma unroll
        for (int u = 0; u < WIN; u++) {
            float4 zv = *(const float4*)&zsh[j + u][4 * gl];
            float w = ew[u];
            acc.x += w * zv.x; acc.y += w * zv.y;
            acc.z += w * zv.z; acc.w += w * zv.w;
        }
        float4 o;
        o.x = acc.x * inv + bv.x;
        o.y = acc.y * inv + bv.y;
        o.z = acc.z * inv + bv.z;
        o.w = acc.w * inv + bv.w;
        *(float4*)&out[(size_t)t * FDIM + 4 * gl] = o;
    }
}

extern "C" void kernel_launch(void* const* d_in, const int* in_sizes, int n_in,
                              void* d_out, int out_size) {
    const float* ori    = (const float*)d_in[0];
    const float* Wfc    = (const float*)d_in[1];
    const float* attn_l = (const float*)d_in[2];
    const float* attn_r = (const float*)d_in[3];
    const float* bias   = (const float*)d_in[4];
    float* out = (float*)d_out;
    int T = in_sizes[0] / FDIM;
    int grid = (T + BT - 1) / BT;
    gat_kernel<<<grid, 256>>>(ori, Wfc, attn_l, attn_r, bias, out, T);
}